// round 2
// baseline (speedup 1.0000x reference)
#include <cuda_runtime.h>

// DTM (distance-to-measure) on a 64x64 integer grid.
// Per (b,c) slice: bound = 0.05 * sum(w). Per point p: walk grid points in
// order of increasing squared distance, accumulate weight until crossing
// bound, output sqrt((sum_{d<d*} d^2 w + d*^2 (bound - cum_before)) / bound).
// Equivalent to the reference top_k formulation (weights >= 0 => crossing is
// always within max_k; value is order-invariant within equal-d^2 groups).

#define HW 4096
#define NSLICE 12
#define NOFF (127 * 127)       // 16129 offsets (dy,dx) in [-63,63]^2
#define ND2 (2 * 63 * 63 + 1)  // 7939 possible d^2 values
#define PREF 2048              // shared-memory prefix of the sorted table

__device__ unsigned g_table[NOFF];  // packed: d2<<14 | (dy+63)<<7 | (dx+63)

// ---- fused table build: hist -> scan -> scatter, all in one block's smem ----

__global__ void __launch_bounds__(1024) k_build() {
    __shared__ int cnt[ND2];     // histogram, then exclusive-prefix cursors
    __shared__ int part[1024];   // block-scan partials
    int t = threadIdx.x;

    for (int i = t; i < ND2; i += 1024) cnt[i] = 0;
    __syncthreads();

    for (int i = t; i < NOFF; i += 1024) {
        int dy = i / 127 - 63;
        int dx = i % 127 - 63;
        atomicAdd(&cnt[dy * dy + dx * dx], 1);
    }
    __syncthreads();

    // serial scan of 8 per thread + Hillis-Steele over 1024 partials
    int base = t * 8;
    int loc[8];
    int s = 0;
#pragma unroll
    for (int k = 0; k < 8; k++) {
        int v = (base + k < ND2) ? cnt[base + k] : 0;
        loc[k] = s;
        s += v;
    }
    part[t] = s;
    __syncthreads();
    for (int off = 1; off < 1024; off <<= 1) {
        int v = (t >= off) ? part[t - off] : 0;
        __syncthreads();
        part[t] += v;
        __syncthreads();
    }
    int pre = (t > 0) ? part[t - 1] : 0;
    __syncthreads();  // all reads of cnt done before overwrite as cursors
#pragma unroll
    for (int k = 0; k < 8; k++)
        if (base + k < ND2) cnt[base + k] = pre + loc[k];
    __syncthreads();

    for (int i = t; i < NOFF; i += 1024) {
        int dy = i / 127 - 63;
        int dx = i % 127 - 63;
        int d2 = dy * dy + dx * dx;
        int pos = atomicAdd(&cnt[d2], 1);
        g_table[pos] = ((unsigned)d2 << 14) | ((unsigned)(dy + 63) << 7) |
                       (unsigned)(dx + 63);
    }
}

// ---- main kernel: one block = (slice, 128-point chunk) ----

__global__ void __launch_bounds__(128)
k_main(const float* __restrict__ x, float* __restrict__ out) {
    __shared__ __align__(16) float sw[HW];
    __shared__ __align__(16) unsigned soff[PREF];   // (dy+63)<<7 | (dx+63)
    __shared__ __align__(16) float sd2[PREF];       // d^2 as float
    __shared__ float wsum[4];

    int slice = blockIdx.x >> 5;  // 32 chunks of 128 points per slice
    int chunk = blockIdx.x & 31;
    const float* src = x + slice * HW;
    int t = threadIdx.x;

    // vectorized slice load + local sum
    float lsum = 0.f;
#pragma unroll
    for (int i = t * 4; i < HW; i += 512) {
        float4 v = *(const float4*)(src + i);
        *(float4*)&sw[i] = v;
        lsum += (v.x + v.y) + (v.z + v.w);
    }
    // split table prefix into offsets + float d^2
    for (int i = t; i < PREF; i += 128) {
        unsigned e = g_table[i];
        soff[i] = e & 0x3FFFu;
        sd2[i] = (float)(e >> 14);
    }
#pragma unroll
    for (int o = 16; o; o >>= 1) lsum += __shfl_xor_sync(0xFFFFFFFFu, lsum, o);
    if ((t & 31) == 0) wsum[t >> 5] = lsum;
    __syncthreads();
    float bound = 0.05f * ((wsum[0] + wsum[1]) + (wsum[2] + wsum[3]));

    int p = (chunk << 7) + t;
    int row = p >> 6;
    int col = p & 63;

    float cum = 0.f, acc = 0.f, res = -1.f;
    int i = 0;

    // fast path over shared prefix, unrolled x4 with group-sum crossing test
    for (; i < PREF; i += 4) {
        uint4 ev = *(const uint4*)&soff[i];
        float4 dv = *(const float4*)&sd2[i];
        unsigned ee[4] = {ev.x, ev.y, ev.z, ev.w};
        float d2f[4] = {dv.x, dv.y, dv.z, dv.w};
        float w[4];
#pragma unroll
        for (int k = 0; k < 4; k++) {
            unsigned e = ee[k];
            int rr = row + (int)(e >> 7) - 63;
            int cc = col + (int)(e & 127u) - 63;
            bool v = ((unsigned)rr < 64u) & ((unsigned)cc < 64u);
            int idx = v ? ((rr << 6) + cc) : 0;
            float ww = sw[idx];
            w[k] = v ? ww : 0.f;
        }
        float s = (w[0] + w[1]) + (w[2] + w[3]);
        if (cum + s >= bound) {
            // elementwise resolve (weights >= 0 => group test is exact up to
            // fp rounding; if no element crosses, keep scanning)
            bool crossed = false;
#pragma unroll
            for (int k = 0; k < 4; k++) {
                if (!crossed) {
                    float nc = cum + w[k];
                    if (nc >= bound) {
                        acc += d2f[k] * (bound - cum);
                        res = acc;
                        crossed = true;
                    } else {
                        cum = nc;
                        acc += d2f[k] * w[k];
                    }
                }
            }
            if (crossed) break;
        } else {
            cum += s;
            acc += d2f[0] * w[0];
            acc += d2f[1] * w[1];
            acc += d2f[2] * w[2];
            acc += d2f[3] * w[3];
        }
    }

    // rare fallback: continue from global table beyond the prefix
    if (res < 0.f) {
        for (; i < NOFF; ++i) {
            unsigned e = g_table[i];
            int rr = row + (int)((e >> 7) & 127u) - 63;
            int cc = col + (int)(e & 127u) - 63;
            bool v = ((unsigned)rr < 64u) & ((unsigned)cc < 64u);
            int idx = v ? ((rr << 6) + cc) : 0;
            float ww = sw[idx];
            ww = v ? ww : 0.f;
            float d2f = (float)(e >> 14);
            float nc = cum + ww;
            if (nc >= bound) {
                acc += d2f * (bound - cum);
                res = acc;
                break;
            }
            cum = nc;
            acc += d2f * ww;
        }
        if (res < 0.f) res = acc;  // rounding guard: never crossed
    }

    out[slice * HW + p] = sqrtf(res / bound);
}

extern "C" void kernel_launch(void* const* d_in, const int* in_sizes, int n_in,
                              void* d_out, int out_size) {
    const float* x = (const float*)d_in[0];
    float* out = (float*)d_out;

    k_build<<<1, 1024>>>();
    k_main<<<NSLICE * 32, 128>>>(x, out);
}

// round 3
// speedup vs baseline: 1.5828x; 1.5828x over previous
#include <cuda_runtime.h>

// DTM (distance-to-measure) on a 64x64 integer grid.
// Per (b,c) slice: bound = 0.05 * sum(w). Per point p: walk grid points in
// order of increasing squared distance, accumulate weight until crossing
// bound, output sqrt((sum_{d<d*} d^2 w + d*^2 (bound - cum_before)) / bound).
// Order within equal-d^2 groups is irrelevant (value is order-invariant),
// so a lexicographic tie rank matches the reference top_k result.

#define HW 4096
#define NSLICE 12
#define NOFF 16129            // (dy,dx) in [-63,63]^2
#define NPAD 16192            // NOFF rounded up to 64
#define MAXD2 7938
#define PITCH 65              // diagonal-banked shared pitch

__device__ __align__(16) unsigned g_table[NPAD];  // d2<<14 | (dy+63)<<7 | (dx+63)

// ---- build: each offset computes its sorted rank in closed form ----

__global__ void __launch_bounds__(256) k_build() {
    __shared__ unsigned char isq[MAXD2 + 1];
    int t = threadIdx.x;
    // isqrt LUT without MUFU: thread s writes isq[v]=s for v in [s^2,(s+1)^2)
    for (int s = t; s <= 89; s += 256) {
        int lo = s * s;
        int hi = (s + 1) * (s + 1);
        if (hi > MAXD2 + 1) hi = MAXD2 + 1;
        for (int v = lo; v < hi; v++) isq[v] = (unsigned char)s;
    }
    __syncthreads();

    int i = blockIdx.x * 256 + t;
    if (i >= NPAD) return;
    if (i >= NOFF) { g_table[i] = 0xFFFFFFFFu; return; }  // pad: always OOB
    int dy = i / 127 - 63;
    int dx = i % 127 - 63;
    int d2 = dy * dy + dx * dx;
    int pos = 0;
    for (int a = -63; a <= 63; a++) {
        int na = d2 - a * a;
        if (na < 0) continue;
        int s = isq[na];
        bool perf = (s * s == na);
        if (na > 0) {                       // count b with b^2 < na, |b|<=63
            int tt = perf ? s - 1 : s;
            if (tt > 63) tt = 63;
            pos += 2 * tt + 1;
        }
        if (perf && s <= 63) {              // ties b = +-s, lex (a,b) order
            if (a < dy) pos += (s == 0) ? 1 : 2;
            else if (a == dy) {
                if (-s < dx) pos++;
                if (s != 0 && s < dx) pos++;
            }
        }
    }
    g_table[pos] =
        ((unsigned)d2 << 14) | ((unsigned)(dy + 63) << 7) | (unsigned)(dx + 63);
}

// ---- main: one warp per point, lanes scan 64 sorted entries per step ----

__global__ void __launch_bounds__(512, 3)
k_main(const float* __restrict__ x, float* __restrict__ out) {
    __shared__ float sw[64 * PITCH];
    __shared__ float sred[16];
    __shared__ float sbound;

    int t = threadIdx.x;
    int slice = blockIdx.x >> 8;   // 256 point-groups of 16 per slice
    int pg = blockIdx.x & 255;
    const float* src = x + slice * HW;

    float lsum = 0.f;
    for (int i = t; i < HW; i += 512) {
        float v = src[i];
        sw[(i >> 6) * PITCH + (i & 63)] = v;
        lsum += v;
    }
#pragma unroll
    for (int o = 16; o; o >>= 1) lsum += __shfl_xor_sync(~0u, lsum, o);
    if ((t & 31) == 0) sred[t >> 5] = lsum;
    __syncthreads();
    if (t == 0) {
        float b = 0.f;
#pragma unroll
        for (int k = 0; k < 16; k++) b += sred[k];
        sbound = 0.05f * b;
    }
    __syncthreads();
    float bound = sbound;

    int w = t >> 5;
    int lane = t & 31;
    int p = (pg << 4) + w;
    int row = p >> 6;
    int col = p & 63;

    float cum = 0.f;   // warp-uniform running weight sum
    float accL = 0.f;  // per-lane distributed d^2*w accumulator

    const uint2* tab = (const uint2*)g_table;
    uint2 ee = __ldg(&tab[lane]);  // double-buffered table stream

    for (int base = 0; base < NPAD; base += 64) {
        int nxt = (base + 64 < NPAD) ? ((base + 64) >> 1) + lane : lane;
        uint2 nx = __ldg(&tab[nxt]);

        unsigned e0 = ee.x, e1 = ee.y;
        int rr0 = row + (int)((e0 >> 7) & 127u) - 63;
        int cc0 = col + (int)(e0 & 127u) - 63;
        bool v0 = ((unsigned)rr0 < 64u) & ((unsigned)cc0 < 64u);
        float w0 = v0 ? sw[rr0 * PITCH + cc0] : 0.f;
        float d20 = (float)(e0 >> 14);
        int rr1 = row + (int)((e1 >> 7) & 127u) - 63;
        int cc1 = col + (int)(e1 & 127u) - 63;
        bool v1 = ((unsigned)rr1 < 64u) & ((unsigned)cc1 < 64u);
        float w1 = v1 ? sw[rr1 * PITCH + cc1] : 0.f;
        float d21 = (float)(e1 >> 14);

        float pair = w0 + w1;
        float sc = pair;  // inclusive warp scan of pair sums
#pragma unroll
        for (int o = 1; o < 32; o <<= 1) {
            float u = __shfl_up_sync(~0u, sc, o);
            if (lane >= o) sc += u;
        }
        float total = __shfl_sync(~0u, sc, 31);

        if (cum + total >= bound) {  // warp-uniform crossing test
            float cumExcl = cum + (sc - pair);  // weight before this pair
            float cA = cumExcl + w0;
            bool x0 = cA >= bound;
            bool x1 = (cA + w1) >= bound;
            unsigned m = __ballot_sync(~0u, x0 | x1);
            if (m) {
                int fl = __ffs(m) - 1;
                if (lane < fl) {
                    accL += d20 * w0 + d21 * w1;
                } else if (lane == fl) {
                    accL += x0 ? d20 * (bound - cumExcl)
                               : d20 * w0 + d21 * (bound - cA);
                }
                break;  // warp-uniform exit
            }
            // rounding edge: group said cross but no element did — keep going
        }
        cum += total;
        accL += d20 * w0 + d21 * w1;
        ee = nx;
    }

#pragma unroll
    for (int o = 16; o; o >>= 1) accL += __shfl_xor_sync(~0u, accL, o);
    if (lane == 0) out[slice * HW + p] = sqrtf(accL / bound);
}

extern "C" void kernel_launch(void* const* d_in, const int* in_sizes, int n_in,
                              void* d_out, int out_size) {
    const float* x = (const float*)d_in[0];
    float* out = (float*)d_out;

    k_build<<<(NPAD + 255) / 256, 256>>>();
    k_main<<<NSLICE * 256, 512>>>(x, out);
}